// round 1
// baseline (speedup 1.0000x reference)
#include <cuda_runtime.h>
#include <cstddef>

// Problem constants
#define BB 2048
#define SS 512
#define EE 48
#define HH 48
#define VV 95
#define GG 144        // 3*H
#define K2 24         // H/2 (float2 pairs over k)
#define BTILE 16
#define NTHREADS 512

// ---- device scratch (precomputed tables; allocation-free rule => __device__ globals) ----
__device__ float  g_Gb[VV * GG];        // Gb[v][g] = sum_k emb[v,k]*w_ih[g,k] + b_ih[g]
__device__ float2 g_whh2[K2 * GG];      // whh2[k2][g] = (w_hh[g][2k2], w_hh[g][2k2+1])
__device__ float2 g_wout2[K2 * 96];     // wout2[k2][v] (v padded to 96 with zeros)

// ---------------- prep kernel: build lookup table + k-major float2 weight layouts ----------------
__global__ void prep_kernel(const float* __restrict__ emb,
                            const float* __restrict__ w_ih,
                            const float* __restrict__ b_ih,
                            const float* __restrict__ w_hh,
                            const float* __restrict__ w_out) {
    int blk = blockIdx.x;
    if (blk < VV) {
        int v = blk;
        for (int g = threadIdx.x; g < GG; g += blockDim.x) {
            float acc = b_ih[g];
            #pragma unroll 8
            for (int k = 0; k < EE; k++)
                acc = fmaf(emb[v * EE + k], w_ih[g * EE + k], acc);
            g_Gb[v * GG + g] = acc;
        }
    } else {
        for (int i = threadIdx.x; i < K2 * GG; i += blockDim.x) {
            int k2 = i / GG, g = i % GG;
            g_whh2[i] = make_float2(w_hh[g * HH + 2 * k2], w_hh[g * HH + 2 * k2 + 1]);
        }
        for (int i = threadIdx.x; i < K2 * 96; i += blockDim.x) {
            int k2 = i / 96, v = i % 96;
            g_wout2[i] = (v < VV)
                ? make_float2(w_out[v * HH + 2 * k2], w_out[v * HH + 2 * k2 + 1])
                : make_float2(0.f, 0.f);
        }
    }
}

// ---------------- fast gate nonlinearities (MUFU-based) ----------------
__device__ __forceinline__ float sigf(float x) {
    return __fdividef(1.f, 1.f + __expf(-x));
}
__device__ __forceinline__ float tanhfast(float x) {
    // exact algebra: (e^{2x}-1)/(e^{2x}+1); saturates correctly at +-inf
    return 1.f - __fdividef(2.f, __expf(2.f * x) + 1.f);
}

// ---------------- shared memory layout (bytes) ----------------
#define OFF_WHH2  0
#define OFF_WOUT2 27648                         // 24*144*8
#define OFF_GB    46080                         // + 24*96*8
#define OFF_TOK   100800                        // + 95*144*4
#define OFF_H     133568                        // + 16*512*4
#define OFF_GH    136640                        // + 16*48*4
#define OFF_BHH   145856                        // + 16*144*4
#define OFF_BOUT  146432                        // + 144*4
#define SMEM_BYTES 146816                       // + 96*4

// ---------------- main fused GRU kernel ----------------
// grid = 128 CTAs, 512 threads; warp w owns batch row (blockIdx.x*16 + w) for the
// whole sequence. All per-step data sharing is warp-private -> only __syncwarp().
__global__ void __launch_bounds__(NTHREADS, 1)
gru_kernel(const int* __restrict__ x,
           const float* __restrict__ b_hh,
           const float* __restrict__ b_out,
           float* __restrict__ out) {
    extern __shared__ char smem[];
    float2* whh2  = (float2*)(smem + OFF_WHH2);
    float2* wout2 = (float2*)(smem + OFF_WOUT2);
    float*  Gb    = (float*) (smem + OFF_GB);
    int*    tok   = (int*)   (smem + OFF_TOK);
    float*  hsh   = (float*) (smem + OFF_H);
    float*  ghsh  = (float*) (smem + OFF_GH);
    float*  bhh   = (float*) (smem + OFF_BHH);
    float*  bout  = (float*) (smem + OFF_BOUT);

    const int tid = threadIdx.x;

    // ---- prologue: coalesced loads into shared ----
    for (int i = tid; i < K2 * GG; i += NTHREADS) whh2[i]  = g_whh2[i];
    for (int i = tid; i < K2 * 96; i += NTHREADS) wout2[i] = g_wout2[i];
    for (int i = tid; i < VV * GG; i += NTHREADS) Gb[i]    = g_Gb[i];
    for (int i = tid; i < BTILE * SS; i += NTHREADS)
        tok[i] = x[(size_t)blockIdx.x * BTILE * SS + i];
    for (int i = tid; i < BTILE * HH; i += NTHREADS) hsh[i] = 0.f;
    if (tid < GG) bhh[tid] = b_hh[tid];
    if (tid >= 256 && tid < 256 + 96) {
        int v = tid - 256;
        bout[v] = (v < VV) ? b_out[v] : 0.f;
    }
    __syncthreads();

    const int w    = tid >> 5;
    const int lane = tid & 31;
    const int bg   = blockIdx.x * BTILE + w;

    const int*   trow = tok  + w * SS;
    float*       hrow = hsh  + w * HH;
    float*       grow = ghsh + w * GG;
    float*       orow = out + (size_t)bg * SS * VV;
    const float2* h2p = (const float2*)hrow;

    // biases hoisted to registers (b_hh folded into gh accumulators, b_out into logits)
    const float bh0 = bhh[lane], bh1 = bhh[32 + lane], bh2 = bhh[64 + lane], bh3 = bhh[96 + lane];
    const float bh4 = (lane < 16) ? bhh[128 + lane] : 0.f;
    const float bo0 = bout[lane], bo1 = bout[32 + lane], bo2 = bout[64 + lane];

    for (int t = 0; t < SS; t++) {
        // ---- phase 1: gh = h @ w_hh^T + b_hh  (g = lane + 32c) ----
        float a0 = bh0, a1 = bh1, a2 = bh2, a3 = bh3, a4 = bh4;
        #pragma unroll
        for (int k2 = 0; k2 < K2; k2++) {
            const float2 h2 = h2p[k2];                 // warp-uniform broadcast
            const float2* wr = whh2 + k2 * GG;
            float2 ww;
            ww = wr[lane];        a0 = fmaf(h2.y, ww.y, fmaf(h2.x, ww.x, a0));
            ww = wr[32 + lane];   a1 = fmaf(h2.y, ww.y, fmaf(h2.x, ww.x, a1));
            ww = wr[64 + lane];   a2 = fmaf(h2.y, ww.y, fmaf(h2.x, ww.x, a2));
            ww = wr[96 + lane];   a3 = fmaf(h2.y, ww.y, fmaf(h2.x, ww.x, a3));
            ww = wr[128 + lane];  a4 = fmaf(h2.y, ww.y, fmaf(h2.x, ww.x, a4)); // lanes>=16: harmless in-smem read, result unused
        }
        grow[lane] = a0; grow[32 + lane] = a1; grow[64 + lane] = a2; grow[96 + lane] = a3;
        if (lane < 16) grow[128 + lane] = a4;
        __syncwarp();

        // ---- phase 2: gates + h update (input proj is a table-row lookup) ----
        const int tk = trow[t];
        const float* gb = Gb + tk * GG;
        {
            const int j = lane;
            float r = sigf(gb[j] + grow[j]);
            float z = sigf(gb[48 + j] + grow[48 + j]);
            float n = tanhfast(fmaf(r, grow[96 + j], gb[96 + j]));
            float hv = hrow[j];
            hrow[j] = fmaf(z, hv - n, n);
        }
        if (lane < 16) {
            const int j = 32 + lane;
            float r = sigf(gb[j] + grow[j]);
            float z = sigf(gb[48 + j] + grow[48 + j]);
            float n = tanhfast(fmaf(r, grow[96 + j], gb[96 + j]));
            float hv = hrow[j];
            hrow[j] = fmaf(z, hv - n, n);
        }
        __syncwarp();

        // ---- phase 3: logits = h_new @ w_out^T + b_out, streamed to gmem ----
        float l0 = bo0, l1 = bo1, l2 = bo2;
        #pragma unroll
        for (int k2 = 0; k2 < K2; k2++) {
            const float2 h2 = h2p[k2];                 // warp-uniform broadcast
            const float2* wr = wout2 + k2 * 96;
            float2 w0 = wr[lane], w1 = wr[32 + lane], w2 = wr[64 + lane];
            l0 = fmaf(h2.y, w0.y, fmaf(h2.x, w0.x, l0));
            l1 = fmaf(h2.y, w1.y, fmaf(h2.x, w1.x, l1));
            l2 = fmaf(h2.y, w2.y, fmaf(h2.x, w2.x, l2));
        }
        float* o = orow + t * VV;
        __stcs(o + lane, l0);
        __stcs(o + 32 + lane, l1);
        if (lane < 31) __stcs(o + 64 + lane, l2);
    }

    // ---- final hidden state: [1, B, H] appended after logits ----
    float* hid = out + (size_t)BB * SS * VV;
    for (int j = lane; j < HH; j += 32)
        hid[(size_t)bg * HH + j] = hrow[j];
}

// ---------------- launch ----------------
extern "C" void kernel_launch(void* const* d_in, const int* in_sizes, int n_in,
                              void* d_out, int out_size) {
    const int*   x     = (const int*)  d_in[0];
    const float* emb   = (const float*)d_in[1];
    const float* w_ih  = (const float*)d_in[2];
    const float* w_hh  = (const float*)d_in[3];
    const float* b_ih  = (const float*)d_in[4];
    const float* b_hh  = (const float*)d_in[5];
    const float* w_out = (const float*)d_in[6];
    const float* b_out = (const float*)d_in[7];
    float* out = (float*)d_out;

    prep_kernel<<<VV + 1, 128>>>(emb, w_ih, b_ih, w_hh, w_out);

    cudaFuncSetAttribute(gru_kernel, cudaFuncAttributeMaxDynamicSharedMemorySize, SMEM_BYTES);
    gru_kernel<<<BB / BTILE, NTHREADS, SMEM_BYTES>>>(x, b_hh, b_out, out);
}

// round 2
// speedup vs baseline: 1.5228x; 1.5228x over previous
#include <cuda_runtime.h>
#include <cstddef>

// Problem constants
#define BB 2048
#define SS 512
#define EE 48
#define HH 48
#define VV 95
#define GG 144        // 3*H
#define K2 24         // H/2 (float2 pairs over k)

#define WARPS 4
#define RPW 4                      // rows per warp
#define ROWS_CTA (WARPS * RPW)     // 16
#define NTHREADS (WARPS * 32)      // 128
#define NCTAS (BB / ROWS_CTA)      // 128

#define H_STR 56                   // padded floats per h row (conflict-free)
#define GH_STR 152                 // padded floats per gh row (conflict-free)

typedef unsigned long long ull;

// ---- device scratch (allocation-free rule => __device__ globals) ----
__device__ float  g_Gb[VV * GG];        // Gb[v][g] = emb[v] @ w_ih^T + b_ih
__device__ float2 g_whh2[K2 * GG];      // whh2[k2][g]
__device__ float2 g_wout2[K2 * 96];     // wout2[k2][v], v padded to 96 with 0

// ---------------- prep kernel ----------------
__global__ void prep_kernel(const float* __restrict__ emb,
                            const float* __restrict__ w_ih,
                            const float* __restrict__ b_ih,
                            const float* __restrict__ w_hh,
                            const float* __restrict__ w_out) {
    int blk = blockIdx.x;
    if (blk < VV) {
        int v = blk;
        for (int g = threadIdx.x; g < GG; g += blockDim.x) {
            float acc = b_ih[g];
            #pragma unroll 8
            for (int k = 0; k < EE; k++)
                acc = fmaf(emb[v * EE + k], w_ih[g * EE + k], acc);
            g_Gb[v * GG + g] = acc;
        }
    } else {
        for (int i = threadIdx.x; i < K2 * GG; i += blockDim.x) {
            int k2 = i / GG, g = i % GG;
            g_whh2[i] = make_float2(w_hh[g * HH + 2 * k2], w_hh[g * HH + 2 * k2 + 1]);
        }
        for (int i = threadIdx.x; i < K2 * 96; i += blockDim.x) {
            int k2 = i / 96, v = i % 96;
            g_wout2[i] = (v < VV)
                ? make_float2(w_out[v * HH + 2 * k2], w_out[v * HH + 2 * k2 + 1])
                : make_float2(0.f, 0.f);
        }
    }
}

// ---------------- helpers ----------------
__device__ __forceinline__ float sigf(float x) {
    return __fdividef(1.f, 1.f + __expf(-x));
}
__device__ __forceinline__ float tanhfast(float x) {
    return 1.f - __fdividef(2.f, __expf(2.f * x) + 1.f);
}
__device__ __forceinline__ void ffma2(ull& acc, ull a, ull b) {
    asm("fma.rn.f32x2 %0, %1, %2, %0;" : "+l"(acc) : "l"(a), "l"(b));
}
__device__ __forceinline__ float hsum2(ull v) {
    return __uint_as_float((unsigned)v) + __uint_as_float((unsigned)(v >> 32));
}
__device__ __forceinline__ ull pack_lo(float f) {     // (f, 0)
    return (ull)__float_as_uint(f);
}

// ---------------- shared memory layout (bytes) ----------------
#define OFF_WHH2  0                                 // float2[24*144]      27648
#define OFF_WOUT2 27648                             // float2[24*96]       18432
#define OFF_GB    46080                             // float[95*144]       54720
#define OFF_TOK   100800                            // int[16*512]         32768
#define OFF_H     133568                            // float[16*56]         3584
#define OFF_GH    137152                            // float[16*152]        9728
#define SMEM_BYTES 146880

// ---------------- main fused GRU kernel ----------------
// 128 CTAs x 128 threads. Warp w owns rows 4w..4w+3 of its CTA's 16-row batch
// tile for the whole sequence; all sharing is warp-private (syncwarp only).
// Per step: [gates] then one merged k-pass computing logits(t) AND gh(t+1)
// from the same h(t) broadcast, with packed f32x2 FMA.
__global__ void __launch_bounds__(NTHREADS)
gru_kernel(const int* __restrict__ x,
           const float* __restrict__ b_hh,
           const float* __restrict__ b_out,
           float* __restrict__ out) {
    extern __shared__ char smem[];
    float2* whh2  = (float2*)(smem + OFF_WHH2);
    float2* wout2 = (float2*)(smem + OFF_WOUT2);
    float*  Gb    = (float*) (smem + OFF_GB);
    int*    tok   = (int*)   (smem + OFF_TOK);
    float*  hsh   = (float*) (smem + OFF_H);
    float*  ghsh  = (float*) (smem + OFF_GH);

    const int tid = threadIdx.x;

    // ---- prologue ----
    for (int i = tid; i < K2 * GG; i += NTHREADS) whh2[i]  = g_whh2[i];
    for (int i = tid; i < K2 * 96; i += NTHREADS) wout2[i] = g_wout2[i];
    for (int i = tid; i < VV * GG; i += NTHREADS) Gb[i]    = g_Gb[i];
    for (int i = tid; i < ROWS_CTA * SS; i += NTHREADS)
        tok[i] = x[(size_t)blockIdx.x * ROWS_CTA * SS + i];
    for (int i = tid; i < ROWS_CTA * H_STR; i += NTHREADS) hsh[i] = 0.f;
    // gh(0) = w_hh @ 0 + b_hh = b_hh
    for (int i = tid; i < ROWS_CTA * GG; i += NTHREADS) {
        int row = i / GG, g = i % GG;
        ghsh[row * GH_STR + g] = b_hh[g];
    }
    __syncthreads();

    const int w    = tid >> 5;
    const int lane = tid & 31;

    // biases -> registers (fold into accumulator init, low half of f32x2)
    float bh[5], bo[3];
    #pragma unroll
    for (int c = 0; c < 4; c++) bh[c] = b_hh[32 * c + lane];
    bh[4] = (lane < 16) ? b_hh[128 + lane] : 0.f;
    #pragma unroll
    for (int c = 0; c < 3; c++) {
        int v = 32 * c + lane;
        bo[c] = (v < VV) ? b_out[v] : 0.f;
    }

    // gate-phase mapping: lane -> (row = lane>>3, jb = lane&7), elems j = jb+8i
    const int grow_ = lane >> 3;
    const int jb    = lane & 7;
    float* hG  = hsh  + (w * RPW + grow_) * H_STR;
    float* ghG = ghsh + (w * RPW + grow_) * GH_STR;
    const int* tokG = tok + (w * RPW + grow_) * SS;

    // merged-pass row bases
    const ull* hq[RPW];
    float*     ghR[RPW];
    float*     outR[RPW];
    #pragma unroll
    for (int r = 0; r < RPW; r++) {
        int rl = w * RPW + r;
        hq[r]  = (const ull*)(hsh + rl * H_STR);
        ghR[r] = ghsh + rl * GH_STR;
        outR[r] = out + (size_t)(blockIdx.x * ROWS_CTA + rl) * SS * VV;
    }

    const ull* wh = (const ull*)whh2;
    const ull* wo = (const ull*)wout2;

    for (int t = 0; t < SS; t++) {
        // ---------- gates: h(t) = GRU(h(t-1), Gb[tok], gh) ----------
        {
            const int tk = tokG[t];
            const float* gb = Gb + tk * GG;
            #pragma unroll
            for (int i = 0; i < 6; i++) {
                const int j = jb + 8 * i;
                float r = sigf(gb[j]      + ghG[j]);
                float z = sigf(gb[48 + j] + ghG[48 + j]);
                float n = tanhfast(fmaf(r, ghG[96 + j], gb[96 + j]));
                float hv = hG[j];
                hG[j] = fmaf(z, hv - n, n);
            }
        }
        __syncwarp();

        // ---------- merged pass: logits(t) = W_out h(t);  gh(t+1) = W_hh h(t) ----------
        ull aG[RPW][5], aL[RPW][3];
        #pragma unroll
        for (int r = 0; r < RPW; r++) {
            #pragma unroll
            for (int c = 0; c < 5; c++) aG[r][c] = pack_lo(bh[c]);
            #pragma unroll
            for (int c = 0; c < 3; c++) aL[r][c] = pack_lo(bo[c]);
        }

        #pragma unroll 2
        for (int k2 = 0; k2 < K2; k2++) {
            ull hb0 = hq[0][k2], hb1 = hq[1][k2], hb2 = hq[2][k2], hb3 = hq[3][k2];
            const ull* whk = wh + k2 * GG;
            const ull* wok = wo + k2 * 96;
            ull w0 = whk[lane], w1 = whk[32 + lane], w2 = whk[64 + lane],
                w3 = whk[96 + lane], w4 = whk[128 + lane];
            ull u0 = wok[lane], u1 = wok[32 + lane], u2 = wok[64 + lane];

            ffma2(aG[0][0], hb0, w0); ffma2(aG[0][1], hb0, w1); ffma2(aG[0][2], hb0, w2);
            ffma2(aG[0][3], hb0, w3); ffma2(aG[0][4], hb0, w4);
            ffma2(aL[0][0], hb0, u0); ffma2(aL[0][1], hb0, u1); ffma2(aL[0][2], hb0, u2);

            ffma2(aG[1][0], hb1, w0); ffma2(aG[1][1], hb1, w1); ffma2(aG[1][2], hb1, w2);
            ffma2(aG[1][3], hb1, w3); ffma2(aG[1][4], hb1, w4);
            ffma2(aL[1][0], hb1, u0); ffma2(aL[1][1], hb1, u1); ffma2(aL[1][2], hb1, u2);

            ffma2(aG[2][0], hb2, w0); ffma2(aG[2][1], hb2, w1); ffma2(aG[2][2], hb2, w2);
            ffma2(aG[2][3], hb2, w3); ffma2(aG[2][4], hb2, w4);
            ffma2(aL[2][0], hb2, u0); ffma2(aL[2][1], hb2, u1); ffma2(aL[2][2], hb2, u2);

            ffma2(aG[3][0], hb3, w0); ffma2(aG[3][1], hb3, w1); ffma2(aG[3][2], hb3, w2);
            ffma2(aG[3][3], hb3, w3); ffma2(aG[3][4], hb3, w4);
            ffma2(aL[3][0], hb3, u0); ffma2(aL[3][1], hb3, u1); ffma2(aL[3][2], hb3, u2);
        }

        // epilogue: horizontal sums -> gh to smem, logits to gmem (streaming)
        #pragma unroll
        for (int r = 0; r < RPW; r++) {
            ghR[r][lane]      = hsum2(aG[r][0]);
            ghR[r][32 + lane] = hsum2(aG[r][1]);
            ghR[r][64 + lane] = hsum2(aG[r][2]);
            ghR[r][96 + lane] = hsum2(aG[r][3]);
            if (lane < 16) ghR[r][128 + lane] = hsum2(aG[r][4]);

            float* o = outR[r] + t * VV;
            __stcs(o + lane,      hsum2(aL[r][0]));
            __stcs(o + 32 + lane, hsum2(aL[r][1]));
            if (lane < 31) __stcs(o + 64 + lane, hsum2(aL[r][2]));
        }
        __syncwarp();
    }

    // ---- final hidden state: [1, B, H] appended after logits ----
    float* hid = out + (size_t)BB * SS * VV;
    #pragma unroll
    for (int r = 0; r < RPW; r++) {
        int rg = blockIdx.x * ROWS_CTA + w * RPW + r;
        const float* hb = hsh + (w * RPW + r) * H_STR;
        if (lane < 32) hid[(size_t)rg * HH + lane] = hb[lane];
        if (lane < 16) hid[(size_t)rg * HH + 32 + lane] = hb[32 + lane];
    }
}

// ---------------- launch ----------------
extern "C" void kernel_launch(void* const* d_in, const int* in_sizes, int n_in,
                              void* d_out, int out_size) {
    const int*   x     = (const int*)  d_in[0];
    const float* emb   = (const float*)d_in[1];
    const float* w_ih  = (const float*)d_in[2];
    const float* w_hh  = (const float*)d_in[3];
    const float* b_ih  = (const float*)d_in[4];
    const float* b_hh  = (const float*)d_in[5];
    const float* w_out = (const float*)d_in[6];
    const float* b_out = (const float*)d_in[7];
    float* out = (float*)d_out;

    prep_kernel<<<VV + 1, 128>>>(emb, w_ih, b_ih, w_hh, w_out);

    cudaFuncSetAttribute(gru_kernel, cudaFuncAttributeMaxDynamicSharedMemorySize, SMEM_BYTES);
    gru_kernel<<<NCTAS, NTHREADS, SMEM_BYTES>>>(x, b_hh, b_out, out);
}

// round 3
// speedup vs baseline: 1.7407x; 1.1431x over previous
#include <cuda_runtime.h>
#include <cstddef>

// Problem constants
#define BB 2048
#define SS 512
#define EE 48
#define HH 48
#define VV 95
#define GG 144        // 3*H
#define K2 24         // H/2 (f32x2 pairs over k)

#define NTHREADS 256
#define ROWS_CTA 16
#define NCTAS (BB / ROWS_CTA)      // 128

#define H_STRU 26                  // ull stride per h row (52 floats)
#define GH_STR 152                 // float stride per gh row
#define OUT_ROWSTRIDE (SS * VV)    // 48640 floats per batch row

typedef unsigned long long ull;

// ---- device scratch (allocation-free rule => __device__ globals) ----
__device__ float g_Gb[VV * GG];    // Gb[v][g] = emb[v] @ w_ih^T + b_ih

// ---------------- prep kernel: fold embedding+input-projection into a 95x144 table ----------------
__global__ void prep_kernel(const float* __restrict__ emb,
                            const float* __restrict__ w_ih,
                            const float* __restrict__ b_ih) {
    int v = blockIdx.x;
    for (int g = threadIdx.x; g < GG; g += blockDim.x) {
        float acc = b_ih[g];
        #pragma unroll 8
        for (int k = 0; k < EE; k++)
            acc = fmaf(emb[v * EE + k], w_ih[g * EE + k], acc);
        g_Gb[v * GG + g] = acc;
    }
}

// ---------------- helpers ----------------
__device__ __forceinline__ float sigf(float x) {
    return __fdividef(1.f, 1.f + __expf(-x));
}
__device__ __forceinline__ float tanhfast(float x) {
    return 1.f - __fdividef(2.f, __expf(2.f * x) + 1.f);
}
__device__ __forceinline__ void ffma2(ull& acc, ull a, ull b) {
    asm("fma.rn.f32x2 %0, %1, %2, %0;" : "+l"(acc) : "l"(a), "l"(b));
}
__device__ __forceinline__ float hsum2(ull v) {
    return __uint_as_float((unsigned)v) + __uint_as_float((unsigned)(v >> 32));
}
__device__ __forceinline__ ull pack_lo(float f) { return (ull)__float_as_uint(f); }
__device__ __forceinline__ ull pack2(float lo, float hi) {
    ull r;
    asm("mov.b64 %0, {%1, %2};" : "=l"(r) : "r"(__float_as_uint(lo)), "r"(__float_as_uint(hi)));
    return r;
}

// ---------------- shared memory layout (bytes) ----------------
#define OFF_GB   0                                  // float[95*144]   54720
#define OFF_TOK  54720                              // int[16*512]     32768
#define OFF_H    87488                              // ull[16*26]       3328
#define OFF_GH   90816                              // float[16*152]    9728
#define SMEM_BYTES 100544

// ---------------- main fused GRU kernel ----------------
// 128 CTAs x 256 threads (8 warps = 2/SMSP). CTA owns 16 batch rows.
// Channel-specialized: global lane c=tid owns one output channel
//   c in [0,144): gh channel (w_hh row c, reg-resident)
//   c in [144,239): logit channel v=c-144 (w_out row v, reg-resident)
// Per step: gates (all threads, 3 elems each) -> barrier ->
//           GEMV pass (h broadcast LDS, reg weights) -> gh STS / logit STG -> barrier.
__global__ void __launch_bounds__(NTHREADS, 1)
gru_kernel(const int* __restrict__ x,
           const float* __restrict__ w_hh,
           const float* __restrict__ b_hh,
           const float* __restrict__ w_out,
           const float* __restrict__ b_out,
           float* __restrict__ out) {
    extern __shared__ char smem[];
    float* Gb  = (float*)(smem + OFF_GB);
    int*   tok = (int*)  (smem + OFF_TOK);
    ull*   hU  = (ull*)  (smem + OFF_H);
    float* hF  = (float*)(smem + OFF_H);
    float* ghF = (float*)(smem + OFF_GH);

    const int tid = threadIdx.x;
    const int c   = tid;                    // owned output channel

    // ---- prologue: smem fill ----
    for (int i = tid; i < VV * GG; i += NTHREADS) Gb[i] = g_Gb[i];
    for (int i = tid; i < ROWS_CTA * SS; i += NTHREADS)
        tok[i] = x[(size_t)blockIdx.x * ROWS_CTA * SS + i];
    for (int i = tid; i < ROWS_CTA * H_STRU; i += NTHREADS) hU[i] = 0ull;
    // gh(0) = W_hh @ 0 + b_hh = b_hh
    for (int i = tid; i < ROWS_CTA * GG; i += NTHREADS)
        ghF[(i / GG) * GH_STR + (i % GG)] = b_hh[i % GG];

    // ---- weights -> registers (one channel per lane) ----
    const bool isGH  = (c < GG);
    const bool isLOG = (c >= GG) && (c < GG + VV);
    const float* wsrc = isGH ? (w_hh + c * HH)
                             : (isLOG ? (w_out + (c - GG) * HH) : w_out);
    float bias = isGH ? b_hh[c] : (isLOG ? b_out[c - GG] : 0.f);

    ull wreg[K2];
    #pragma unroll
    for (int q = 0; q < 12; q++) {
        float4 f = ((const float4*)wsrc)[q];
        wreg[2 * q]     = pack2(f.x, f.y);
        wreg[2 * q + 1] = pack2(f.z, f.w);
    }
    const ull accInit = pack_lo(bias);

    __syncthreads();

    // gates mapping: thread -> (row = tid>>4, j = (tid&15) + 16i)
    const int grow = tid >> 4;
    const int jb   = tid & 15;
    const int* tokR = tok + grow * SS;
    float* ghR = ghF + grow * GH_STR;
    float* hR  = hF  + grow * (H_STRU * 2);

    // logit store base
    float* outB = out + (size_t)blockIdx.x * ROWS_CTA * OUT_ROWSTRIDE;
    const int v = c - GG;

    for (int t = 0; t < SS; t++) {
        // ---------- gates: h(t) = GRU(h(t-1), Gb[tok], gh(t)) ----------
        {
            const float* gb = Gb + tokR[t] * GG;
            #pragma unroll
            for (int i = 0; i < 3; i++) {
                const int j = jb + 16 * i;
                float r = sigf(gb[j]      + ghR[j]);
                float z = sigf(gb[48 + j] + ghR[48 + j]);
                float n = tanhfast(fmaf(r, ghR[96 + j], gb[96 + j]));
                float hv = hR[j];
                hR[j] = fmaf(z, hv - n, n);
            }
        }
        __syncthreads();

        // ---------- GEMV pass: for each row r, acc[r] = w[c] . h(t)[r] ----------
        ull acc[ROWS_CTA];
        #pragma unroll
        for (int r = 0; r < ROWS_CTA; r++) acc[r] = accInit;

        #pragma unroll
        for (int r = 0; r < ROWS_CTA; r++) {
            const longlong2* h2 = (const longlong2*)(hU + r * H_STRU);
            #pragma unroll
            for (int q = 0; q < 12; q++) {
                longlong2 hv = h2[q];               // broadcast LDS.128
                ffma2(acc[r], (ull)hv.x, wreg[2 * q]);
                ffma2(acc[r], (ull)hv.y, wreg[2 * q + 1]);
            }
        }

        // ---------- epilogue: gh(t+1) -> smem, logits(t) -> gmem ----------
        if (isGH) {
            float* ghc = ghF + c;
            #pragma unroll
            for (int r = 0; r < ROWS_CTA; r++)
                ghc[r * GH_STR] = hsum2(acc[r]);
        } else if (isLOG) {
            float* o = outB + t * VV + v;
            #pragma unroll
            for (int r = 0; r < ROWS_CTA; r++)
                __stcs(o + r * OUT_ROWSTRIDE, hsum2(acc[r]));
        }
        __syncthreads();
    }

    // ---- final hidden state: [1, B, H] appended after logits ----
    float* hid = out + (size_t)BB * SS * VV + (size_t)blockIdx.x * ROWS_CTA * HH;
    #pragma unroll
    for (int i = 0; i < 3; i++) {
        const int j = jb + 16 * i;
        hid[grow * HH + j] = hR[j];
    }
}

// ---------------- launch ----------------
extern "C" void kernel_launch(void* const* d_in, const int* in_sizes, int n_in,
                              void* d_out, int out_size) {
    const int*   x     = (const int*)  d_in[0];
    const float* emb   = (const float*)d_in[1];
    const float* w_ih  = (const float*)d_in[2];
    const float* w_hh  = (const float*)d_in[3];
    const float* b_ih  = (const float*)d_in[4];
    const float* b_hh  = (const float*)d_in[5];
    const float* w_out = (const float*)d_in[6];
    const float* b_out = (const float*)d_in[7];
    float* out = (float*)d_out;

    prep_kernel<<<VV, 128>>>(emb, w_ih, b_ih);

    cudaFuncSetAttribute(gru_kernel, cudaFuncAttributeMaxDynamicSharedMemorySize, SMEM_BYTES);
    gru_kernel<<<NCTAS, NTHREADS, SMEM_BYTES>>>(x, w_hh, b_hh, w_out, b_out, out);
}

// round 4
// speedup vs baseline: 1.7960x; 1.0317x over previous
#include <cuda_runtime.h>
#include <cstddef>

// Problem constants
#define BB 2048
#define SS 512
#define EE 48
#define HH 48
#define VV 95
#define GG 144        // 3*H
#define K2 24         // H/2 (f32x2 pairs over k)

#define NTHREADS 128
#define ROWS_CTA 8
#define NCTAS (BB / ROWS_CTA)      // 256

#define H_STRU 26                  // ull stride per h row (52 floats)
#define GH_STR 152                 // float stride per gh row
#define OUT_ROWSTRIDE (SS * VV)    // 48640 floats per batch row

typedef unsigned long long ull;

// ---- device scratch (allocation-free rule => __device__ globals) ----
__device__ float g_Gb[VV * GG];    // Gb[v][g] = emb[v] @ w_ih^T + b_ih

// ---------------- prep kernel: fold embedding+input projection into 95x144 table ----------------
__global__ void prep_kernel(const float* __restrict__ emb,
                            const float* __restrict__ w_ih,
                            const float* __restrict__ b_ih) {
    int v = blockIdx.x;
    for (int g = threadIdx.x; g < GG; g += blockDim.x) {
        float acc = b_ih[g];
        #pragma unroll 8
        for (int k = 0; k < EE; k++)
            acc = fmaf(emb[v * EE + k], w_ih[g * EE + k], acc);
        g_Gb[v * GG + g] = acc;
    }
}

// ---------------- helpers ----------------
__device__ __forceinline__ float sigf(float x) {
    return __fdividef(1.f, 1.f + __expf(-x));
}
__device__ __forceinline__ float tanhfast(float x) {
    return 1.f - __fdividef(2.f, __expf(2.f * x) + 1.f);
}
__device__ __forceinline__ void ffma2(ull& acc, ull a, ull b) {
    asm("fma.rn.f32x2 %0, %1, %2, %0;" : "+l"(acc) : "l"(a), "l"(b));
}
__device__ __forceinline__ float hsum2(ull v) {
    return __uint_as_float((unsigned)v) + __uint_as_float((unsigned)(v >> 32));
}
__device__ __forceinline__ ull pack_lo(float f) { return (ull)__float_as_uint(f); }
__device__ __forceinline__ ull pack2(float lo, float hi) {
    ull r;
    asm("mov.b64 %0, {%1, %2};" : "=l"(r) : "r"(__float_as_uint(lo)), "r"(__float_as_uint(hi)));
    return r;
}

// ---------------- shared memory layout (bytes) ----------------
#define OFF_GB   0                                  // float[95*144]   54720
#define OFF_TOK  54720                              // int[8*512]      16384
#define OFF_H    71104                              // ull[8*26]        1664
#define OFF_GH   72768                              // float[8*152]     4864
#define SMEM_BYTES 77632

// ---------------- main fused GRU kernel ----------------
// 256 CTAs x 128 threads, 2 CTAs/SM (8 warps/SM). CTA owns 8 batch rows.
// Channel-PAIR specialization: thread t owns channels (2t, 2t+1):
//   c < 144          : gh channels (w_hh rows, reg-resident)
//   144 <= c < 239   : logit channels v=c-144 (w_out rows, reg-resident)
// Each broadcast h load feeds TWO ffma2 (one per owned channel), halving the
// L1 wavefront count per FLOP vs 1-channel threads.
__global__ void __launch_bounds__(NTHREADS, 2)
gru_kernel(const int* __restrict__ x,
           const float* __restrict__ w_hh,
           const float* __restrict__ b_hh,
           const float* __restrict__ w_out,
           const float* __restrict__ b_out,
           float* __restrict__ out) {
    extern __shared__ char smem[];
    float* Gb  = (float*)(smem + OFF_GB);
    int*   tok = (int*)  (smem + OFF_TOK);
    ull*   hU  = (ull*)  (smem + OFF_H);
    float* hF  = (float*)(smem + OFF_H);
    float* ghF = (float*)(smem + OFF_GH);

    const int tid = threadIdx.x;
    const int c0  = 2 * tid;                 // owned channel pair (c0, c0+1)

    // ---- prologue: smem fill ----
    for (int i = tid; i < VV * GG; i += NTHREADS) Gb[i] = g_Gb[i];
    for (int i = tid; i < ROWS_CTA * SS; i += NTHREADS)
        tok[i] = x[(size_t)blockIdx.x * ROWS_CTA * SS + i];
    for (int i = tid; i < ROWS_CTA * H_STRU; i += NTHREADS) hU[i] = 0ull;
    // gh(0) = W_hh @ 0 + b_hh = b_hh
    for (int i = tid; i < ROWS_CTA * GG; i += NTHREADS)
        ghF[(i / GG) * GH_STR + (i % GG)] = b_hh[i % GG];

    // ---- weight pair -> registers ----
    const bool isGH  = (c0 < GG);
    const bool isLOG = (c0 >= GG) && (c0 < GG + VV);
    const int  v0    = c0 - GG;                    // logit index if isLOG
    const bool v1ok  = isLOG && (v0 + 1 < VV);     // mask the v=95 pad channel

    const float* wsA = isGH ? (w_hh + c0 * HH)
                            : (isLOG ? (w_out + v0 * HH) : w_out);
    const float* wsB = isGH ? (w_hh + (c0 + 1) * HH)
                            : (v1ok ? (w_out + (v0 + 1) * HH) : wsA);
    float biasA = isGH ? b_hh[c0]     : (isLOG ? b_out[v0]     : 0.f);
    float biasB = isGH ? b_hh[c0 + 1] : (v1ok  ? b_out[v0 + 1] : 0.f);

    ull wA[K2], wB[K2];
    #pragma unroll
    for (int q = 0; q < 12; q++) {
        float4 fa = ((const float4*)wsA)[q];
        float4 fb = ((const float4*)wsB)[q];
        wA[2 * q]     = pack2(fa.x, fa.y);
        wA[2 * q + 1] = pack2(fa.z, fa.w);
        wB[2 * q]     = pack2(fb.x, fb.y);
        wB[2 * q + 1] = pack2(fb.z, fb.w);
    }
    const ull accA0 = pack_lo(biasA);
    const ull accB0 = pack_lo(biasB);

    __syncthreads();

    // gates mapping: thread -> (row = tid>>4 in [0,8), j = (tid&15) + 16i)
    const int grow = tid >> 4;
    const int jb   = tid & 15;
    const int* tokR = tok + grow * SS;
    float* ghR = ghF + grow * GH_STR;
    float* hR  = hF  + grow * (H_STRU * 2);

    float* outB = out + (size_t)blockIdx.x * ROWS_CTA * OUT_ROWSTRIDE;

    for (int t = 0; t < SS; t++) {
        // ---------- gates: h(t) = GRU(h(t-1), Gb[tok], gh(t)) ----------
        {
            const float* gb = Gb + tokR[t] * GG;
            #pragma unroll
            for (int i = 0; i < 3; i++) {
                const int j = jb + 16 * i;
                float r = sigf(gb[j]      + ghR[j]);
                float z = sigf(gb[48 + j] + ghR[48 + j]);
                float n = tanhfast(fmaf(r, ghR[96 + j], gb[96 + j]));
                float hv = hR[j];
                hR[j] = fmaf(z, hv - n, n);
            }
        }
        __syncthreads();

        // ---------- GEMV: both owned channels dot every row's h(t) ----------
        #pragma unroll
        for (int r = 0; r < ROWS_CTA; r++) {
            const longlong2* h2 = (const longlong2*)(hU + r * H_STRU);
            ull aA = accA0, aB = accB0;
            #pragma unroll
            for (int q = 0; q < 12; q++) {
                longlong2 hv = h2[q];               // broadcast LDS.128, feeds 4 ffma2
                ffma2(aA, (ull)hv.x, wA[2 * q]);
                ffma2(aB, (ull)hv.x, wB[2 * q]);
                ffma2(aA, (ull)hv.y, wA[2 * q + 1]);
                ffma2(aB, (ull)hv.y, wB[2 * q + 1]);
            }
            float resA = hsum2(aA), resB = hsum2(aB);

            if (isGH) {
                // paired STS.64 (c0 even, row stride 152 floats -> 8B aligned)
                *(float2*)(ghF + r * GH_STR + c0) = make_float2(resA, resB);
            } else if (isLOG) {
                float* o = outB + r * OUT_ROWSTRIDE + t * VV + v0;
                __stcs(o, resA);
                if (v1ok) __stcs(o + 1, resB);
            }
        }
        __syncthreads();
    }

    // ---- final hidden state: [1, B, H] appended after logits ----
    float* hid = out + (size_t)BB * SS * VV + (size_t)blockIdx.x * ROWS_CTA * HH;
    #pragma unroll
    for (int i = 0; i < 3; i++) {
        const int j = jb + 16 * i;
        hid[grow * HH + j] = hR[j];
    }
}

// ---------------- launch ----------------
extern "C" void kernel_launch(void* const* d_in, const int* in_sizes, int n_in,
                              void* d_out, int out_size) {
    const int*   x     = (const int*)  d_in[0];
    const float* emb   = (const float*)d_in[1];
    const float* w_ih  = (const float*)d_in[2];
    const float* w_hh  = (const float*)d_in[3];
    const float* b_ih  = (const float*)d_in[4];
    const float* b_hh  = (const float*)d_in[5];
    const float* w_out = (const float*)d_in[6];
    const float* b_out = (const float*)d_in[7];
    float* out = (float*)d_out;

    prep_kernel<<<VV, 128>>>(emb, w_ih, b_ih);

    cudaFuncSetAttribute(gru_kernel, cudaFuncAttributeMaxDynamicSharedMemorySize, SMEM_BYTES);
    gru_kernel<<<NCTAS, NTHREADS, SMEM_BYTES>>>(x, w_hh, b_hh, w_out, b_out, out);
}

// round 6
// speedup vs baseline: 1.9329x; 1.0763x over previous
#include <cuda_runtime.h>
#include <cstddef>

// Problem constants
#define BB 2048
#define SS 512
#define EE 48
#define HH 48
#define VV 95
#define GG 144        // 3*H
#define NCH 239       // 144 gh + 95 logit channels

#define NTHREADS 256
#define ROWS_CTA 8
#define NCTAS (BB / ROWS_CTA)      // 256

#define H_STRU 26                  // ull stride per h row (52 floats)
#define GH_STR 152                 // float stride per gh row
#define OUT_ROWSTRIDE (SS * VV)    // 48640 floats per batch row

typedef unsigned long long ull;

// ---- device scratch (allocation-free rule => __device__ globals) ----
__device__ float g_Gb[VV * GG];    // Gb[v][g] = emb[v] @ w_ih^T + b_ih

// ---------------- prep kernel: fold embedding+input projection into 95x144 table ----------------
__global__ void prep_kernel(const float* __restrict__ emb,
                            const float* __restrict__ w_ih,
                            const float* __restrict__ b_ih) {
    int v = blockIdx.x;
    for (int g = threadIdx.x; g < GG; g += blockDim.x) {
        float acc = b_ih[g];
        #pragma unroll 8
        for (int k = 0; k < EE; k++)
            acc = fmaf(emb[v * EE + k], w_ih[g * EE + k], acc);
        g_Gb[v * GG + g] = acc;
    }
}

// ---------------- helpers ----------------
__device__ __forceinline__ float sigf(float x) {
    return __fdividef(1.f, 1.f + __expf(-x));
}
__device__ __forceinline__ float tanhfast(float x) {
    return 1.f - __fdividef(2.f, __expf(2.f * x) + 1.f);
}
__device__ __forceinline__ void ffma2(ull& acc, ull a, ull b) {
    asm("fma.rn.f32x2 %0, %1, %2, %0;" : "+l"(acc) : "l"(a), "l"(b));
}
__device__ __forceinline__ float hsum2(ull v) {
    return __uint_as_float((unsigned)v) + __uint_as_float((unsigned)(v >> 32));
}
__device__ __forceinline__ ull pack_lo(float f) { return (ull)__float_as_uint(f); }
__device__ __forceinline__ ull pack2(float lo, float hi) {
    ull r;
    asm("mov.b64 %0, {%1, %2};" : "=l"(r) : "r"(__float_as_uint(lo)), "r"(__float_as_uint(hi)));
    return r;
}

// ---------------- shared memory layout (bytes) ----------------
#define OFF_GB   0                                  // float[95*144]   54720
#define OFF_TOK  54720                              // int[8*512]      16384
#define OFF_H    71104                              // ull[8*26]        1664
#define OFF_GH   72768                              // float[8*152]     4864
#define SMEM_BYTES 77632

// ---------------- main fused GRU kernel ----------------
// 256 CTAs x 256 threads, 2 CTAs/SM => 16 warps/SM (4 per SMSP).
// Lane-pair channel ownership with k-split:
//   pair u = tid>>1 owns channels (2u, 2u+1); even lane (half=0) holds the
//   k in [0,24) weight half, odd lane k in [24,48). 48 weight regs/thread.
//   Partials combined with ONE shfl.bfly(1) per channel per row.
// Gates: warp w owns batch row w (uniform token/gb addressing).
__global__ void __launch_bounds__(NTHREADS, 2)
gru_kernel(const int* __restrict__ x,
           const float* __restrict__ w_hh,
           const float* __restrict__ b_hh,
           const float* __restrict__ w_out,
           const float* __restrict__ b_out,
           float* __restrict__ out) {
    extern __shared__ char smem[];
    float* Gb  = (float*)(smem + OFF_GB);
    int*   tok = (int*)  (smem + OFF_TOK);
    ull*   hU  = (ull*)  (smem + OFF_H);
    float* hF  = (float*)(smem + OFF_H);
    float* ghF = (float*)(smem + OFF_GH);

    const int tid  = threadIdx.x;
    const int wid  = tid >> 5;
    const int lane = tid & 31;

    // ---- prologue: smem fill ----
    for (int i = tid; i < VV * GG; i += NTHREADS) Gb[i] = g_Gb[i];
    for (int i = tid; i < ROWS_CTA * SS; i += NTHREADS)
        tok[i] = x[(size_t)blockIdx.x * ROWS_CTA * SS + i];
    for (int i = tid; i < ROWS_CTA * H_STRU; i += NTHREADS) hU[i] = 0ull;
    // gh(0) = W_hh @ 0 + b_hh = b_hh
    for (int i = tid; i < ROWS_CTA * GG; i += NTHREADS)
        ghF[(i / GG) * GH_STR + (i % GG)] = b_hh[i % GG];

    // ---- channel-pair / k-half setup ----
    const int u    = tid >> 1;          // pair id
    const int half = tid & 1;           // k-half: 0 -> k[0:24), 1 -> k[24:48)
    const int cA   = 2 * u;
    const int cB   = 2 * u + 1;
    const int myc  = cA + half;         // channel this lane STORES (= tid & ~1 | half = tid... consecutive)

    // clamped weight row pointers (invalid channels read row 0 of w_out, masked at store)
    const float* wsA = (cA < GG) ? (w_hh + cA * HH)
                                 : (w_out + ((cA < NCH) ? (cA - GG) : 0) * HH);
    const float* wsB = (cB < GG) ? (w_hh + cB * HH)
                                 : (w_out + ((cB < NCH) ? (cB - GG) : 0) * HH);
    // biases: added once, in the even lane's accumulator init
    float biasA = 0.f, biasB = 0.f;
    if (half == 0) {
        biasA = (cA < GG) ? b_hh[cA] : ((cA < NCH) ? b_out[cA - GG] : 0.f);
        biasB = (cB < GG) ? b_hh[cB] : ((cB < NCH) ? b_out[cB - GG] : 0.f);
    }

    ull wA[12], wB[12];
    #pragma unroll
    for (int q = 0; q < 6; q++) {
        float4 fa = ((const float4*)wsA)[half * 6 + q];
        float4 fb = ((const float4*)wsB)[half * 6 + q];
        wA[2 * q]     = pack2(fa.x, fa.y);
        wA[2 * q + 1] = pack2(fa.z, fa.w);
        wB[2 * q]     = pack2(fb.x, fb.y);
        wB[2 * q + 1] = pack2(fb.z, fb.w);
    }
    const ull accA0 = pack_lo(biasA);
    const ull accB0 = pack_lo(biasB);

    __syncthreads();

    // gates: warp wid owns row wid
    const int* tokR = tok + wid * SS;
    float* ghW = ghF + wid * GH_STR;
    float* hW  = hF  + wid * (H_STRU * 2);

    float* outB = out + (size_t)blockIdx.x * ROWS_CTA * OUT_ROWSTRIDE;
    const bool storeGH  = (myc < GG);
    const bool storeLOG = (myc >= GG) && (myc < NCH);
    float* outC = outB + (myc - GG);     // logit column base (valid iff storeLOG)
    float* ghC  = ghF + myc;             // gh column base (valid iff storeGH)

    for (int t = 0; t < SS; t++) {
        // ---------- gates: h(t) = GRU(h(t-1), Gb[tok], gh(t)), warp-per-row ----------
        {
            const float* gb = Gb + tokR[t] * GG;     // warp-uniform
            {
                const int j = lane;
                float r = sigf(gb[j]      + ghW[j]);
                float z = sigf(gb[48 + j] + ghW[48 + j]);
                float n = tanhfast(fmaf(r, ghW[96 + j], gb[96 + j]));
                float hv = hW[j];
                hW[j] = fmaf(z, hv - n, n);
            }
            if (lane < 16) {
                const int j = 32 + lane;
                float r = sigf(gb[j]      + ghW[j]);
                float z = sigf(gb[48 + j] + ghW[48 + j]);
                float n = tanhfast(fmaf(r, ghW[96 + j], gb[96 + j]));
                float hv = hW[j];
                hW[j] = fmaf(z, hv - n, n);
            }
        }
        __syncthreads();

        // ---------- GEMV: each lane, its k-half of both owned channels, all rows ----------
        #pragma unroll
        for (int r = 0; r < ROWS_CTA; r++) {
            const longlong2* h2 = (const longlong2*)(hU + r * H_STRU + half * 12);
            ull aA = accA0, aB = accB0;
            #pragma unroll
            for (int q = 0; q < 6; q++) {
                longlong2 hv = h2[q];                // 16B broadcast (2 addr/warp)
                ffma2(aA, (ull)hv.x, wA[2 * q]);
                ffma2(aB, (ull)hv.x, wB[2 * q]);
                ffma2(aA, (ull)hv.y, wA[2 * q + 1]);
                ffma2(aB, (ull)hv.y, wB[2 * q + 1]);
            }
            float pA = hsum2(aA);
            float pB = hsum2(aB);
            // one exchange completes both channels:
            // even lane needs odd's pA; odd lane needs even's pB
            float send = half ? pA : pB;
            float recv = __shfl_xor_sync(0xffffffffu, send, 1);
            float res  = (half ? pB : pA) + recv;    // full dot of channel myc

            if (storeGH) {
                ghC[r * GH_STR] = res;
            } else if (storeLOG) {
                __stcs(outC + r * OUT_ROWSTRIDE + t * VV, res);
            }
        }
        __syncthreads();
    }

    // ---- final hidden state: [1, B, H] appended after logits ----
    float* hid = out + (size_t)BB * SS * VV
               + (size_t)(blockIdx.x * ROWS_CTA + wid) * HH;
    hid[lane] = hW[lane];
    if (lane < 16) hid[32 + lane] = hW[32 + lane];
}

// ---------------- launch ----------------
extern "C" void kernel_launch(void* const* d_in, const int* in_sizes, int n_in,
                              void* d_out, int out_size) {
    const int*   x     = (const int*)  d_in[0];
    const float* emb   = (const float*)d_in[1];
    const float* w_ih  = (const float*)d_in[2];
    const float* w_hh  = (const float*)d_in[3];
    const float* b_ih  = (const float*)d_in[4];
    const float* b_hh  = (const float*)d_in[5];
    const float* w_out = (const float*)d_in[6];
    const float* b_out = (const float*)d_in[7];
    float* out = (float*)d_out;

    prep_kernel<<<VV, 128>>>(emb, w_ih, b_ih);

    cudaFuncSetAttribute(gru_kernel, cudaFuncAttributeMaxDynamicSharedMemorySize, SMEM_BYTES);
    gru_kernel<<<NCTAS, NTHREADS, SMEM_BYTES>>>(x, w_hh, b_hh, w_out, b_out, out);
}

// round 10
// speedup vs baseline: 2.1299x; 1.1019x over previous
#include <cuda_runtime.h>
#include <cstddef>

// Problem constants
#define BB 2048
#define SS 512
#define EE 48
#define HH 48
#define VV 95
#define GG 144        // 3*H
#define NCH 239       // 144 gh + 95 logit channels

#define NTHREADS 256
#define ROWS_CTA 7
#define NCTAS 296                  // exactly 2 CTAs per SM (148 SMs)
// CTA b owns batch rows b + 296*r, r in [0,7); rows >= 2048 masked.

#define H_STRU 28                  // ull stride per h row (56 floats)
#define GH_STR 152                 // float stride per gh row
#define TOK_STR 8                  // tokens stored [t][row]
#define OUT_ROWSTRIDE (SS * VV)    // 48640 floats per batch row

typedef unsigned long long ull;

// ---- device scratch ----
__device__ float g_Gb[VV * GG];    // Gb[v][g] = emb[v] @ w_ih^T + b_ih

// ---------------- prep kernel ----------------
__global__ void prep_kernel(const float* __restrict__ emb,
                            const float* __restrict__ w_ih,
                            const float* __restrict__ b_ih) {
    int v = blockIdx.x;
    for (int g = threadIdx.x; g < GG; g += blockDim.x) {
        float acc = b_ih[g];
        #pragma unroll 8
        for (int k = 0; k < EE; k++)
            acc = fmaf(emb[v * EE + k], w_ih[g * EE + k], acc);
        g_Gb[v * GG + g] = acc;
    }
}

// ---------------- helpers ----------------
__device__ __forceinline__ float sigf(float x) {
    return __fdividef(1.f, 1.f + __expf(-x));
}
__device__ __forceinline__ float tanhfast(float x) {
    return 1.f - __fdividef(2.f, __expf(2.f * x) + 1.f);
}
__device__ __forceinline__ void ffma2(ull& acc, ull a, ull b) {
    asm("fma.rn.f32x2 %0, %1, %2, %0;" : "+l"(acc) : "l"(a), "l"(b));
}
__device__ __forceinline__ float hsum2(ull v) {
    return __uint_as_float((unsigned)v) + __uint_as_float((unsigned)(v >> 32));
}
__device__ __forceinline__ ull pack_lo(float f) { return (ull)__float_as_uint(f); }
__device__ __forceinline__ ull pack2(float lo, float hi) {
    ull r;
    asm("mov.b64 %0, {%1, %2};" : "=l"(r) : "r"(__float_as_uint(lo)), "r"(__float_as_uint(hi)));
    return r;
}

// ---------------- shared memory layout (bytes) ----------------
#define OFF_GB   0                                  // float[95*144]    54720
#define OFF_TOK  54720                              // int[512*8]       16384
#define OFF_H    71104                              // ull[7*28]         1568
#define OFF_GH   72672                              // float[7*152]      4256
#define SMEM_BYTES 76928

// ---------------- main fused GRU kernel ----------------
// 296 CTAs x 256 threads, exactly 2 CTAs/SM. CTA b owns rows {b + 296r}.
// Lane-pair channel ownership with k-split (same as the 948us baseline):
//   pair u=tid>>1 owns channels (2u,2u+1); even lane holds k[0:24) weights,
//   odd lane k[24:48); one shfl.bfly(1) completes both channels per row.
// Gates: warp w (<7) owns row w. Two __syncthreads per step.
__global__ void __launch_bounds__(NTHREADS, 2)
gru_kernel(const int* __restrict__ x,
           const float* __restrict__ w_hh,
           const float* __restrict__ b_hh,
           const float* __restrict__ w_out,
           const float* __restrict__ b_out,
           float* __restrict__ out) {
    extern __shared__ char smem[];
    float* Gb   = (float*)(smem + OFF_GB);
    int*   tokT = (int*)  (smem + OFF_TOK);
    ull*   hU   = (ull*)  (smem + OFF_H);
    float* hF   = (float*)(smem + OFF_H);
    float* ghF  = (float*)(smem + OFF_GH);

    const int tid  = threadIdx.x;
    const int wid  = tid >> 5;
    const int lane = tid & 31;
    const int b    = blockIdx.x;

    // row table: gRow[r] = b + 296*r, clamped; validity mask per r
    int  gRow[ROWS_CTA];
    bool vOK[ROWS_CTA];
    #pragma unroll
    for (int r = 0; r < ROWS_CTA; r++) {
        int gr = b + NCTAS * r;
        vOK[r]  = (gr < BB);
        gRow[r] = vOK[r] ? gr : 0;
    }

    // ---- prologue ----
    for (int i = tid; i < VV * GG; i += NTHREADS) Gb[i] = g_Gb[i];
    // tokens: read coalesced over t per row, store [t][r]
    for (int i = tid; i < ROWS_CTA * SS; i += NTHREADS) {
        int r = i >> 9, t = i & (SS - 1);
        tokT[t * TOK_STR + r] = x[(size_t)gRow[r] * SS + t];
    }
    for (int i = tid; i < ROWS_CTA * H_STRU; i += NTHREADS) hU[i] = 0ull;
    // gh(0) = b_hh
    for (int i = tid; i < ROWS_CTA * GG; i += NTHREADS)
        ghF[(i / GG) * GH_STR + (i % GG)] = b_hh[i % GG];

    // ---- channel-pair / k-half setup ----
    const int half = tid & 1;
    const int u    = tid >> 1;
    const int cA   = 2 * u;
    const int cB   = 2 * u + 1;
    const int myc  = cA + half;

    const float* wsA = (cA < GG) ? (w_hh + cA * HH)
                                 : (w_out + ((cA < NCH) ? (cA - GG) : 0) * HH);
    const float* wsB = (cB < GG) ? (w_hh + cB * HH)
                                 : (w_out + ((cB < NCH) ? (cB - GG) : 0) * HH);
    float biasA = 0.f, biasB = 0.f;
    if (half == 0) {
        biasA = (cA < GG) ? b_hh[cA] : ((cA < NCH) ? b_out[cA - GG] : 0.f);
        biasB = (cB < GG) ? b_hh[cB] : ((cB < NCH) ? b_out[cB - GG] : 0.f);
    }

    ull wA[12], wB[12];
    #pragma unroll
    for (int q = 0; q < 6; q++) {
        float4 fa = ((const float4*)wsA)[half * 6 + q];
        float4 fb = ((const float4*)wsB)[half * 6 + q];
        wA[2 * q]     = pack2(fa.x, fa.y);
        wA[2 * q + 1] = pack2(fa.z, fa.w);
        wB[2 * q]     = pack2(fb.x, fb.y);
        wB[2 * q + 1] = pack2(fb.z, fb.w);
    }
    const ull accA0 = pack_lo(biasA);
    const ull accB0 = pack_lo(biasB);

    __syncthreads();

    // gates: warp wid owns row wid (warp 7 idles through gates)
    const bool gateW = (wid < ROWS_CTA);
    float* ghW = ghF + wid * GH_STR;
    float* hW  = hF  + wid * (H_STRU * 2);

    const bool storeGH  = (myc < GG);
    const bool storeLOG = (myc >= GG) && (myc < NCH);
    // per-row logit store pointers (column myc-GG of each owned batch row)
    float* outR[ROWS_CTA];
    #pragma unroll
    for (int r = 0; r < ROWS_CTA; r++)
        outR[r] = out + (size_t)gRow[r] * OUT_ROWSTRIDE + (storeLOG ? (myc - GG) : 0);
    float* ghC = ghF + myc;

    for (int t = 0; t < SS; t++) {
        // ---------- gates: h(t) = GRU(h(t-1), Gb[tok], gh(t)), warp-per-row ----------
        if (gateW) {
            const float* gb = Gb + tokT[t * TOK_STR + wid] * GG;   // warp-uniform
            {
                const int j = lane;
                float r = sigf(gb[j]      + ghW[j]);
                float z = sigf(gb[48 + j] + ghW[48 + j]);
                float n = tanhfast(fmaf(r, ghW[96 + j], gb[96 + j]));
                float hv = hW[j];
                hW[j] = fmaf(z, hv - n, n);
            }
            if (lane < 16) {
                const int j = 32 + lane;
                float r = sigf(gb[j]      + ghW[j]);
                float z = sigf(gb[48 + j] + ghW[48 + j]);
                float n = tanhfast(fmaf(r, ghW[96 + j], gb[96 + j]));
                float hv = hW[j];
                hW[j] = fmaf(z, hv - n, n);
            }
        }
        __syncthreads();

        // ---------- GEMV: each lane, its k-half of both owned channels, all rows ----------
        #pragma unroll
        for (int r = 0; r < ROWS_CTA; r++) {
            const longlong2* h2 = (const longlong2*)(hU + r * H_STRU + half * 12);
            ull aA = accA0, aB = accB0;
            #pragma unroll
            for (int q = 0; q < 6; q++) {
                longlong2 hv = h2[q];
                ffma2(aA, (ull)hv.x, wA[2 * q]);
                ffma2(aB, (ull)hv.x, wB[2 * q]);
                ffma2(aA, (ull)hv.y, wA[2 * q + 1]);
                ffma2(aB, (ull)hv.y, wB[2 * q + 1]);
            }
            float pA = hsum2(aA), pB = hsum2(aB);
            float send = half ? pA : pB;
            float recv = __shfl_xor_sync(0xffffffffu, send, 1);
            float res  = (half ? pB : pA) + recv;

            if (storeGH) {
                ghC[r * GH_STR] = res;
            } else if (storeLOG && vOK[r]) {
                __stcs(outR[r] + t * VV, res);
            }
        }
        __syncthreads();
    }

    // ---- final hidden state: [1, B, H] appended after logits ----
    float* hid = out + (size_t)BB * SS * VV;
    for (int i = tid; i < ROWS_CTA * HH; i += NTHREADS) {
        int r = i / HH, j = i % HH;
        if (vOK[r]) hid[(size_t)gRow[r] * HH + j] = hF[r * (H_STRU * 2) + j];
    }
}

// ---------------- launch ----------------
extern "C" void kernel_launch(void* const* d_in, const int* in_sizes, int n_in,
                              void* d_out, int out_size) {
    const int*   x     = (const int*)  d_in[0];
    const float* emb   = (const float*)d_in[1];
    const float* w_ih  = (const float*)d_in[2];
    const float* w_hh  = (const float*)d_in[3];
    const float* b_ih  = (const float*)d_in[4];
    const float* b_hh  = (const float*)d_in[5];
    const float* w_out = (const float*)d_in[6];
    const float* b_out = (const float*)d_in[7];
    float* out = (float*)d_out;

    prep_kernel<<<VV, 128>>>(emb, w_ih, b_ih);

    cudaFuncSetAttribute(gru_kernel, cudaFuncAttributeMaxDynamicSharedMemorySize, SMEM_BYTES);
    gru_kernel<<<NCTAS, NTHREADS, SMEM_BYTES>>>(x, w_hh, b_hh, w_out, b_out, out);
}

// round 13
// speedup vs baseline: 2.1300x; 1.0000x over previous
#include <cuda_runtime.h>
#include <cstddef>

// Problem constants
#define BB 2048
#define SS 512
#define EE 48
#define HH 48
#define VV 95
#define GG 144        // 3*H

#define NTHREADS 256
#define ROWS_CTA 7
#define NCTAS 296                  // exactly 2 CTAs/SM; CTA b owns rows {b + 296r}
#define GH_TH 160                  // gh group: warps 0-4
#define LG_TH 96                   // logit group: warps 5-7

#define H_STRU 28                  // ull stride per h row (56 floats)
#define HBUF_U (ROWS_CTA * H_STRU) // ulls per h buffer
#define GH_STR 152                 // float stride per gh row
#define TOK_STR 8                  // tokens stored [t][row]
#define OUT_ROWSTRIDE (SS * VV)    // 48640 floats per batch row

typedef unsigned long long ull;

// ---- device scratch ----
__device__ float g_Gb[VV * GG];    // Gb[v][g] = emb[v] @ w_ih^T + b_ih

// ---------------- prep kernel ----------------
__global__ void prep_kernel(const float* __restrict__ emb,
                            const float* __restrict__ w_ih,
                            const float* __restrict__ b_ih) {
    int v = blockIdx.x;
    for (int g = threadIdx.x; g < GG; g += blockDim.x) {
        float acc = b_ih[g];
        #pragma unroll 8
        for (int k = 0; k < EE; k++)
            acc = fmaf(emb[v * EE + k], w_ih[g * EE + k], acc);
        g_Gb[v * GG + g] = acc;
    }
}

// ---------------- helpers ----------------
__device__ __forceinline__ float sigf(float x) {
    return __fdividef(1.f, 1.f + __expf(-x));
}
__device__ __forceinline__ float tanhfast(float x) {
    return 1.f - __fdividef(2.f, __expf(2.f * x) + 1.f);
}
__device__ __forceinline__ void ffma2(ull& acc, ull a, ull b) {
    asm("fma.rn.f32x2 %0, %1, %2, %0;" : "+l"(acc) : "l"(a), "l"(b));
}
__device__ __forceinline__ float hsum2(ull v) {
    return __uint_as_float((unsigned)v) + __uint_as_float((unsigned)(v >> 32));
}
__device__ __forceinline__ ull pack_lo(float f) { return (ull)__float_as_uint(f); }
__device__ __forceinline__ ull pack2(float lo, float hi) {
    ull r;
    asm("mov.b64 %0, {%1, %2};" : "=l"(r) : "r"(__float_as_uint(lo)), "r"(__float_as_uint(hi)));
    return r;
}
#define BAR_SYNC(id, cnt)   asm volatile("bar.sync %0, %1;"   :: "r"(id), "r"(cnt) : "memory")
#define BAR_ARRIVE(id, cnt) asm volatile("bar.arrive %0, %1;" :: "r"(id), "r"(cnt) : "memory")

// ---------------- shared memory layout (bytes) ----------------
#define OFF_GB   0                                  // float[95*144]    54720
#define OFF_TOK  54720                              // int[512*8]       16384
#define OFF_H    71104                              // ull[2][7][28]     3136
#define OFF_GH   74240                              // float[7*152]      4256
#define SMEM_BYTES 78496

// ---------------- main fused GRU kernel ----------------
// 296 CTAs x 256 threads, 2 CTAs/SM. CTA b owns rows {b + 296r} (tail masked).
// Warp specialization: warps 0-4 (160) = gates + gh GEMV (recurrence-critical);
// warps 5-7 (96) = logit GEMV, trailing by up to 2 steps on double-buffered h.
// PARITY-SPLIT barriers (strict alternation by causality):
//   bar1 (160): gh-internal     bar 2+(t&1) (256): h(t) ready (gh arr, lg sync)
//   bar 4+(t&1) (256): h buf free (lg arr, gh sync for t>=2)
// FIX vs R11: logit store offset uses the LOCAL vocab index myc (0..94),
// not myc-GG (that shifted every logit 144 floats low -> rel_err 1.4).
__global__ void __launch_bounds__(NTHREADS, 2)
gru_kernel(const int* __restrict__ x,
           const float* __restrict__ w_hh,
           const float* __restrict__ b_hh,
           const float* __restrict__ w_out,
           const float* __restrict__ b_out,
           float* __restrict__ out) {
    extern __shared__ char smem[];
    float* Gb   = (float*)(smem + OFF_GB);
    int*   tokT = (int*)  (smem + OFF_TOK);
    ull*   hU   = (ull*)  (smem + OFF_H);          // [2][7][28]
    float* hF   = (float*)(smem + OFF_H);
    float* ghF  = (float*)(smem + OFF_GH);

    const int tid = threadIdx.x;
    const int b   = blockIdx.x;

    // strided row table (perfect chip balance)
    int  gRow[ROWS_CTA];
    bool vOK[ROWS_CTA];
    #pragma unroll
    for (int r = 0; r < ROWS_CTA; r++) {
        int gr = b + NCTAS * r;
        vOK[r]  = (gr < BB);
        gRow[r] = vOK[r] ? gr : 0;
    }

    // ---- prologue ----
    for (int i = tid; i < VV * GG; i += NTHREADS) Gb[i] = g_Gb[i];
    for (int i = tid; i < ROWS_CTA * SS; i += NTHREADS) {
        int r = i >> 9, t = i & (SS - 1);
        tokT[t * TOK_STR + r] = x[(size_t)gRow[r] * SS + t];
    }
    for (int i = tid; i < 2 * HBUF_U; i += NTHREADS) hU[i] = 0ull;
    for (int i = tid; i < ROWS_CTA * GG; i += NTHREADS)
        ghF[(i / GG) * GH_STR + (i % GG)] = b_hh[i % GG];

    const bool isGHgrp = (tid < GH_TH);

    // ---- channel / weight setup (pair + k-split) ----
    const int half = tid & 1;
    int myc; const float *wsA, *wsB; float biasA = 0.f, biasB = 0.f;
    bool storeOK;
    if (isGHgrp) {
        int u  = tid >> 1;                  // valid < 72
        int cA = 2 * u, cB = 2 * u + 1;
        bool ok = (cB < GG);
        wsA = w_hh + (ok ? cA : 0) * HH;
        wsB = w_hh + (ok ? cB : 0) * HH;
        if (half == 0 && ok) { biasA = b_hh[cA]; biasB = b_hh[cB]; }
        myc = cA + half;                    // gh channel index [0,144)
        storeOK = ok;
    } else {
        int u  = (tid - GH_TH) >> 1;        // 0..47
        int v0 = 2 * u, v1 = 2 * u + 1;
        bool okB = (v1 < VV);
        wsA = w_out + v0 * HH;
        wsB = w_out + (okB ? v1 : v0) * HH;
        if (half == 0) { biasA = b_out[v0]; biasB = okB ? b_out[v1] : 0.f; }
        myc = v0 + half;                    // LOCAL vocab index [0,96)
        storeOK = (myc < VV);
    }

    ull wA[12], wB[12];
    #pragma unroll
    for (int q = 0; q < 6; q++) {
        float4 fa = ((const float4*)wsA)[half * 6 + q];
        float4 fb = ((const float4*)wsB)[half * 6 + q];
        wA[2 * q]     = pack2(fa.x, fa.y);
        wA[2 * q + 1] = pack2(fa.z, fa.w);
        wB[2 * q]     = pack2(fb.x, fb.y);
        wB[2 * q + 1] = pack2(fb.z, fb.w);
    }
    const ull accA0 = pack_lo(biasA);
    const ull accB0 = pack_lo(biasB);

    // gate slots (gh group): elems e = tid + 160*s over 7*48 = 336
    int grow0 = 0, gj0 = 0, grow1 = 0, gj1 = 0, grow2 = 0, gj2 = 0;
    bool gs2 = false;
    if (isGHgrp) {
        grow0 = tid / 48;            gj0 = tid % 48;                   // e0 < 160
        int e1 = tid + 160;          grow1 = e1 / 48; gj1 = e1 % 48;   // e1 < 320
        int e2 = tid + 320;
        gs2 = (e2 < ROWS_CTA * 48);  grow2 = gs2 ? e2 / 48 : 0; gj2 = gs2 ? e2 % 48 : 0;
    }

    __syncthreads();

    if (isGHgrp) {
        // ================= gh group: recurrence-critical loop =================
        for (int t = 0; t < SS; t++) {
            if (t >= 2) BAR_SYNC(4 + (t & 1), NTHREADS);   // buf[t&1] free (logit done t-2)

            // ---- gates: h(t) = GRU(h(t-1), Gb[tok], gh(t)) ----
            {
                float* hOLD = hF + ((t + 1) & 1) * (HBUF_U * 2);
                float* hNEW = hF + (t & 1) * (HBUF_U * 2);
                const int* tks = tokT + t * TOK_STR;

                #define GATE(row, j) {                                         \
                    const float* gb = Gb + tks[row] * GG;                      \
                    float* ghR = ghF + (row) * GH_STR;                         \
                    float r = sigf(gb[j] + ghR[j]);                            \
                    float z = sigf(gb[48 + (j)] + ghR[48 + (j)]);              \
                    float n = tanhfast(fmaf(r, ghR[96 + (j)], gb[96 + (j)])); \
                    float hv = hOLD[(row) * (H_STRU * 2) + (j)];               \
                    hNEW[(row) * (H_STRU * 2) + (j)] = fmaf(z, hv - n, n); }
                GATE(grow0, gj0);
                GATE(grow1, gj1);
                if (gs2) GATE(grow2, gj2);
                #undef GATE
            }
            BAR_SYNC(1, GH_TH);                            // h(t) done within gh group
            BAR_ARRIVE(2 + (t & 1), NTHREADS);             // publish h(t)

            // ---- gh GEMV: gh(t+1) = W_hh h(t) + b_hh ----
            const ull* hbase = hU + (t & 1) * HBUF_U;
            #pragma unroll
            for (int r = 0; r < ROWS_CTA; r++) {
                const longlong2* h2 = (const longlong2*)(hbase + r * H_STRU + half * 12);
                ull aA = accA0, aB = accB0;
                #pragma unroll
                for (int q = 0; q < 6; q++) {
                    longlong2 hv = h2[q];
                    ffma2(aA, (ull)hv.x, wA[2 * q]);
                    ffma2(aB, (ull)hv.x, wB[2 * q]);
                    ffma2(aA, (ull)hv.y, wA[2 * q + 1]);
                    ffma2(aB, (ull)hv.y, wB[2 * q + 1]);
                }
                float pA = hsum2(aA), pB = hsum2(aB);
                float send = half ? pA : pB;
                float recv = __shfl_xor_sync(0xffffffffu, send, 1);
                float res  = (half ? pB : pA) + recv;
                if (storeOK) ghF[r * GH_STR + myc] = res;
            }
            BAR_SYNC(1, GH_TH);                            // gh(t+1) ready
        }
    } else {
        // ================= logit group: trails by up to 2 steps =================
        float* outR[ROWS_CTA];
        #pragma unroll
        for (int r = 0; r < ROWS_CTA; r++)
            outR[r] = out + (size_t)gRow[r] * OUT_ROWSTRIDE + (storeOK ? myc : 0);

        for (int t = 0; t < SS; t++) {
            BAR_SYNC(2 + (t & 1), NTHREADS);               // h(t) ready
            const ull* hbase = hU + (t & 1) * HBUF_U;
            #pragma unroll
            for (int r = 0; r < ROWS_CTA; r++) {
                const longlong2* h2 = (const longlong2*)(hbase + r * H_STRU + half * 12);
                ull aA = accA0, aB = accB0;
                #pragma unroll
                for (int q = 0; q < 6; q++) {
                    longlong2 hv = h2[q];
                    ffma2(aA, (ull)hv.x, wA[2 * q]);
                    ffma2(aB, (ull)hv.x, wB[2 * q]);
                    ffma2(aA, (ull)hv.y, wA[2 * q + 1]);
                    ffma2(aB, (ull)hv.y, wB[2 * q + 1]);
                }
                float pA = hsum2(aA), pB = hsum2(aB);
                float send = half ? pA : pB;
                float recv = __shfl_xor_sync(0xffffffffu, send, 1);
                float res  = (half ? pB : pA) + recv;
                if (storeOK && vOK[r])
                    __stcs(outR[r] + t * VV, res);
            }
            if (t < SS - 2) BAR_ARRIVE(4 + (t & 1), NTHREADS);  // buf[t&1] free
        }
    }

    // ---- final hidden state: [1, B, H]; h(511) lives in buf[1] ----
    __syncthreads();
    float* hid = out + (size_t)BB * SS * VV;
    const float* hFin = hF + 1 * (HBUF_U * 2);
    for (int i = tid; i < ROWS_CTA * HH; i += NTHREADS) {
        int r = i / HH, j = i % HH;
        if (vOK[r]) hid[(size_t)gRow[r] * HH + j] = hFin[r * (H_STRU * 2) + j];
    }
}

// ---------------- launch ----------------
extern "C" void kernel_launch(void* const* d_in, const int* in_sizes, int n_in,
                              void* d_out, int out_size) {
    const int*   x     = (const int*)  d_in[0];
    const float* emb   = (const float*)d_in[1];
    const float* w_ih  = (const float*)d_in[2];
    const float* w_hh  = (const float*)d_in[3];
    const float* b_ih  = (const float*)d_in[4];
    const float* b_hh  = (const float*)d_in[5];
    const float* w_out = (const float*)d_in[6];
    const float* b_out = (const float*)d_in[7];
    float* out = (float*)d_out;

    prep_kernel<<<VV, 128>>>(emb, w_ih, b_ih);

    cudaFuncSetAttribute(gru_kernel, cudaFuncAttributeMaxDynamicSharedMemorySize, SMEM_BYTES);
    gru_kernel<<<NCTAS, NTHREADS, SMEM_BYTES>>>(x, w_hh, b_hh, w_out, b_out, out);
}

// round 17
// speedup vs baseline: 2.2552x; 1.0588x over previous
#include <cuda_runtime.h>
#include <cstddef>

// Problem constants
#define BB 2048
#define SS 512
#define EE 48
#define HH 48
#define VV 95
#define GG 144        // 3*H
#define NCH 239       // 144 gh + 95 logit channels

#define NTHREADS 256
#define ROWS_CTA 7
#define NCTAS 296                  // exactly 2 CTAs per SM (148 SMs)
// CTA b owns batch rows b + 296*r, r in [0,7); rows >= 2048 masked.

#define H_STRU 28                  // ull stride per h row (56 floats)
#define GH_STR 152                 // float stride per gh row
#define TOK_STR 8                  // tokens stored [t][row]
#define OUT_ROWSTRIDE (SS * VV)    // 48640 floats per batch row

typedef unsigned long long ull;

// ---- device scratch ----
__device__ float g_Gb[VV * GG];    // Gb[v][g] = emb[v] @ w_ih^T + b_ih

// ---------------- prep kernel ----------------
__global__ void prep_kernel(const float* __restrict__ emb,
                            const float* __restrict__ w_ih,
                            const float* __restrict__ b_ih) {
    int v = blockIdx.x;
    for (int g = threadIdx.x; g < GG; g += blockDim.x) {
        float acc = b_ih[g];
        #pragma unroll 8
        for (int k = 0; k < EE; k++)
            acc = fmaf(emb[v * EE + k], w_ih[g * EE + k], acc);
        g_Gb[v * GG + g] = acc;
    }
}

// ---------------- helpers ----------------
__device__ __forceinline__ float tanhapx(float x) {       // MUFU.TANH, 1 op
    float y;
    asm("tanh.approx.f32 %0, %1;" : "=f"(y) : "f"(x));
    return y;
}
__device__ __forceinline__ float sigapx(float x) {        // sig(x)=.5*tanh(.5x)+.5
    return fmaf(0.5f, tanhapx(0.5f * x), 0.5f);
}
__device__ __forceinline__ void ffma2(ull& acc, ull a, ull b) {
    asm("fma.rn.f32x2 %0, %1, %2, %0;" : "+l"(acc) : "l"(a), "l"(b));
}
__device__ __forceinline__ float hsum2(ull v) {
    return __uint_as_float((unsigned)v) + __uint_as_float((unsigned)(v >> 32));
}
__device__ __forceinline__ ull pack_lo(float f) { return (ull)__float_as_uint(f); }
__device__ __forceinline__ ull pack2(float lo, float hi) {
    ull r;
    asm("mov.b64 %0, {%1, %2};" : "=l"(r) : "r"(__float_as_uint(lo)), "r"(__float_as_uint(hi)));
    return r;
}

// ---------------- shared memory layout (bytes) ----------------
#define OFF_GB   0                                  // float[95*144]    54720
#define OFF_TOK  54720                              // int[512*8]       16384
#define OFF_H    71104                              // ull[7*28]         1568
#define OFF_GH   72672                              // float[7*152]      4256
#define SMEM_BYTES 76928

// ---------------- main fused GRU kernel ----------------
// 296 CTAs x 256 threads, exactly 2 CTAs/SM. CTA b owns rows {b + 296r}.
// Lane-pair channel ownership with k-split; gates warp-per-row with
// HW tanh.approx for all nonlinearities (3 MUFU/elem, short chains).
__global__ void __launch_bounds__(NTHREADS, 2)
gru_kernel(const int* __restrict__ x,
           const float* __restrict__ w_hh,
           const float* __restrict__ b_hh,
           const float* __restrict__ w_out,
           const float* __restrict__ b_out,
           float* __restrict__ out) {
    extern __shared__ char smem[];
    float* Gb   = (float*)(smem + OFF_GB);
    int*   tokT = (int*)  (smem + OFF_TOK);
    ull*   hU   = (ull*)  (smem + OFF_H);
    float* hF   = (float*)(smem + OFF_H);
    float* ghF  = (float*)(smem + OFF_GH);

    const int tid  = threadIdx.x;
    const int wid  = tid >> 5;
    const int lane = tid & 31;
    const int b    = blockIdx.x;

    // strided row table (perfect chip balance)
    int  gRow[ROWS_CTA];
    bool vOK[ROWS_CTA];
    #pragma unroll
    for (int r = 0; r < ROWS_CTA; r++) {
        int gr = b + NCTAS * r;
        vOK[r]  = (gr < BB);
        gRow[r] = vOK[r] ? gr : 0;
    }

    // ---- prologue ----
    for (int i = tid; i < VV * GG; i += NTHREADS) Gb[i] = g_Gb[i];
    for (int i = tid; i < ROWS_CTA * SS; i += NTHREADS) {
        int r = i >> 9, t = i & (SS - 1);
        tokT[t * TOK_STR + r] = x[(size_t)gRow[r] * SS + t];
    }
    for (int i = tid; i < ROWS_CTA * H_STRU; i += NTHREADS) hU[i] = 0ull;
    for (int i = tid; i < ROWS_CTA * GG; i += NTHREADS)
        ghF[(i / GG) * GH_STR + (i % GG)] = b_hh[i % GG];

    // ---- channel-pair / k-half setup ----
    const int half = tid & 1;
    const int u    = tid >> 1;
    const int cA   = 2 * u;
    const int cB   = 2 * u + 1;
    const int myc  = cA + half;

    const float* wsA = (cA < GG) ? (w_hh + cA * HH)
                                 : (w_out + ((cA < NCH) ? (cA - GG) : 0) * HH);
    const float* wsB = (cB < GG) ? (w_hh + cB * HH)
                                 : (w_out + ((cB < NCH) ? (cB - GG) : 0) * HH);
    float biasA = 0.f, biasB = 0.f;
    if (half == 0) {
        biasA = (cA < GG) ? b_hh[cA] : ((cA < NCH) ? b_out[cA - GG] : 0.f);
        biasB = (cB < GG) ? b_hh[cB] : ((cB < NCH) ? b_out[cB - GG] : 0.f);
    }

    ull wA[12], wB[12];
    #pragma unroll
    for (int q = 0; q < 6; q++) {
        float4 fa = ((const float4*)wsA)[half * 6 + q];
        float4 fb = ((const float4*)wsB)[half * 6 + q];
        wA[2 * q]     = pack2(fa.x, fa.y);
        wA[2 * q + 1] = pack2(fa.z, fa.w);
        wB[2 * q]     = pack2(fb.x, fb.y);
        wB[2 * q + 1] = pack2(fb.z, fb.w);
    }
    const ull accA0 = pack_lo(biasA);
    const ull accB0 = pack_lo(biasB);

    __syncthreads();

    // gates: warp wid owns row wid (warp 7 idles through gates)
    const bool gateW = (wid < ROWS_CTA);
    float* ghW = ghF + wid * GH_STR;
    float* hW  = hF  + wid * (H_STRU * 2);

    const bool storeGH  = (myc < GG);
    const bool storeLOG = (myc >= GG) && (myc < NCH);
    float* outR[ROWS_CTA];
    #pragma unroll
    for (int r = 0; r < ROWS_CTA; r++)
        outR[r] = out + (size_t)gRow[r] * OUT_ROWSTRIDE + (storeLOG ? (myc - GG) : 0);
    float* ghC = ghF + myc;

    // token prefetch (gate warps): tok for t=0
    int tokCur = 0;
    if (gateW) tokCur = tokT[0 * TOK_STR + wid];

    for (int t = 0; t < SS; t++) {
        // ---------- gates: h(t) = GRU(h(t-1), Gb[tok], gh(t)), warp-per-row ----------
        if (gateW) {
            const float* gb = Gb + tokCur * GG;      // warp-uniform
            {
                const int j = lane;
                float r = sigapx(gb[j]      + ghW[j]);
                float z = sigapx(gb[48 + j] + ghW[48 + j]);
                float n = tanhapx(fmaf(r, ghW[96 + j], gb[96 + j]));
                float hv = hW[j];
                hW[j] = fmaf(z, hv - n, n);
            }
            if (lane < 16) {
                const int j = 32 + lane;
                float r = sigapx(gb[j]      + ghW[j]);
                float z = sigapx(gb[48 + j] + ghW[48 + j]);
                float n = tanhapx(fmaf(r, ghW[96 + j], gb[96 + j]));
                float hv = hW[j];
                hW[j] = fmaf(z, hv - n, n);
            }
            if (t + 1 < SS) tokCur = tokT[(t + 1) * TOK_STR + wid];  // prefetch next token
        }
        __syncthreads();

        // ---------- GEMV: each lane, its k-half of both owned channels, all rows ----------
        #pragma unroll
        for (int r = 0; r < ROWS_CTA; r++) {
            const longlong2* h2 = (const longlong2*)(hU + r * H_STRU + half * 12);
            ull aA = accA0, aB = accB0;
            #pragma unroll
            for (int q = 0; q < 6; q++) {
                longlong2 hv = h2[q];
                ffma2(aA, (ull)hv.x, wA[2 * q]);
                ffma2(aB, (ull)hv.x, wB[2 * q]);
                ffma2(aA, (ull)hv.y, wA[2 * q + 1]);
                ffma2(aB, (ull)hv.y, wB[2 * q + 1]);
            }
            float pA = hsum2(aA), pB = hsum2(aB);
            float send = half ? pA : pB;
            float recv = __shfl_xor_sync(0xffffffffu, send, 1);
            float res  = (half ? pB : pA) + recv;

            if (storeGH) {
                ghC[r * GH_STR] = res;
            } else if (storeLOG && vOK[r]) {
                __stcs(outR[r] + t * VV, res);
            }
        }
        __syncthreads();
    }

    // ---- final hidden state: [1, B, H] appended after logits ----
    float* hid = out + (size_t)BB * SS * VV;
    for (int i = tid; i < ROWS_CTA * HH; i += NTHREADS) {
        int r = i / HH, j = i % HH;
        if (vOK[r]) hid[(size_t)gRow[r] * HH + j] = hF[r * (H_STRU * 2) + j];
    }
}

// ---------------- launch ----------------
extern "C" void kernel_launch(void* const* d_in, const int* in_sizes, int n_in,
                              void* d_out, int out_size) {
    const int*   x     = (const int*)  d_in[0];
    const float* emb   = (const float*)d_in[1];
    const float* w_ih  = (const float*)d_in[2];
    const float* w_hh  = (const float*)d_in[3];
    const float* b_ih  = (const float*)d_in[4];
    const float* b_hh  = (const float*)d_in[5];
    const float* w_out = (const float*)d_in[6];
    const float* b_out = (const float*)d_in[7];
    float* out = (float*)d_out;

    prep_kernel<<<VV, 128>>>(emb, w_ih, b_ih);

    cudaFuncSetAttribute(gru_kernel, cudaFuncAttributeMaxDynamicSharedMemorySize, SMEM_BYTES);
    gru_kernel<<<NCTAS, NTHREADS, SMEM_BYTES>>>(x, w_hh, b_hh, w_out, b_out, out);
}